// round 14
// baseline (speedup 1.0000x reference)
#include <cuda_runtime.h>
#include <cuda_fp16.h>
#include <cstdint>
#include <cstddef>

#define D_MODEL 2048
#define N_EXP 8
#define T_TOK 8192
#define BM 128
#define BN 256
#define BK 64
#define KIT (D_MODEL / BK)
#define NTHREADS 512
#define LOSS_SCALE 3e-06f
#define ROUTER_BLOCKS (T_TOK / 32)   /* 256: one warp per 4 tokens */
#define CONV_BLOCKS 8192

// ---------------- device global scratch (no allocations allowed) ------------
__device__ int   g_cnt[N_EXP];
__device__ int   g_cur[N_EXP];
__device__ float g_tsum[N_EXP];
__device__ int   g_idx[T_TOK];
__device__ float g_topp[T_TOK];
__device__ int   g_list[T_TOK];

// fp16 copies, precomputed once per launch
__device__ __half g_Wh[(size_t)N_EXP * D_MODEL * D_MODEL];
__device__ __half g_Xh[(size_t)T_TOK * D_MODEL];

// ---------------- helpers ----------------------------------------------------
__device__ __forceinline__ uint32_t smem_u32(const void* p) {
    uint32_t a;
    asm("{ .reg .u64 t; cvta.to.shared.u64 t, %1; cvt.u32.u64 %0, t; }"
        : "=r"(a) : "l"(p));
    return a;
}

#define CP_ASYNC16(dst, src) \
    asm volatile("cp.async.cg.shared.global [%0], [%1], 16;" \
        :: "r"(dst), "l"(src))
#define CP_COMMIT() asm volatile("cp.async.commit_group;")
#define CP_WAIT2()  asm volatile("cp.async.wait_group 2;")

__device__ __forceinline__ void ldsm4(uint32_t& r0, uint32_t& r1, uint32_t& r2,
                                      uint32_t& r3, uint32_t addr) {
    asm volatile("ldmatrix.sync.aligned.m8n8.x4.shared.b16 {%0,%1,%2,%3}, [%4];"
                 : "=r"(r0), "=r"(r1), "=r"(r2), "=r"(r3) : "r"(addr));
}

__device__ __forceinline__ void mma16816(float* c, const uint32_t* a,
                                         uint32_t b0, uint32_t b1) {
    asm volatile(
        "mma.sync.aligned.m16n8k16.row.col.f32.f16.f16.f32 "
        "{%0,%1,%2,%3}, {%4,%5,%6,%7}, {%8,%9}, {%0,%1,%2,%3};"
        : "+f"(c[0]), "+f"(c[1]), "+f"(c[2]), "+f"(c[3])
        : "r"(a[0]), "r"(a[1]), "r"(a[2]), "r"(a[3]), "r"(b0), "r"(b1));
}

// ---------------- small kernels ----------------------------------------------
__global__ void init_kernel() {
    int i = threadIdx.x;
    if (i < N_EXP) { g_cnt[i] = 0; g_cur[i] = 0; g_tsum[i] = 0.f; }
}

// Fused kernel: blocks [0, ROUTER_BLOCKS) run the router (+ x->fp16 store),
// blocks [ROUTER_BLOCKS, ...) convert W to fp16.
__global__ void router_convert_kernel(const float* __restrict__ x,
                                      const float* __restrict__ Wr,
                                      const float* __restrict__ br,
                                      const float4* __restrict__ W4) {
    if (blockIdx.x >= ROUTER_BLOCKS) {
        uint2* wh2 = reinterpret_cast<uint2*>(g_Wh);
        const int n4 = N_EXP * D_MODEL * D_MODEL / 4;
        int bi = blockIdx.x - ROUTER_BLOCKS;
        for (int i = bi * blockDim.x + threadIdx.x; i < n4;
             i += CONV_BLOCKS * blockDim.x) {
            float4 v = W4[i];
            __half2 h0 = __floats2half2_rn(v.x, v.y);
            __half2 h1 = __floats2half2_rn(v.z, v.w);
            uint2 o;
            o.x = *(uint32_t*)&h0;
            o.y = *(uint32_t*)&h1;
            wh2[i] = o;
        }
        return;
    }

    // ---- router path: one warp per 4 tokens ----
    int warp = (blockIdx.x * blockDim.x + threadIdx.x) >> 5;
    int lane = threadIdx.x & 31;
    int t0 = warp * 4;
    if (t0 >= T_TOK) return;

    const float4* x4 = reinterpret_cast<const float4*>(x);
    const float4* w4 = reinterpret_cast<const float4*>(Wr);
    uint2* xh2 = reinterpret_cast<uint2*>(g_Xh);

    float acc[4][N_EXP];
#pragma unroll
    for (int t = 0; t < 4; t++)
#pragma unroll
        for (int e = 0; e < N_EXP; e++) acc[t][e] = 0.f;

    for (int j = lane; j < D_MODEL / 4; j += 32) {
        float4 w[N_EXP];
#pragma unroll
        for (int e = 0; e < N_EXP; e++) w[e] = w4[e * (D_MODEL / 4) + j];
#pragma unroll
        for (int t = 0; t < 4; t++) {
            float4 v = x4[(size_t)(t0 + t) * (D_MODEL / 4) + j];
            __half2 h0 = __floats2half2_rn(v.x, v.y);
            __half2 h1 = __floats2half2_rn(v.z, v.w);
            uint2 o;
            o.x = *(uint32_t*)&h0;
            o.y = *(uint32_t*)&h1;
            xh2[(size_t)(t0 + t) * (D_MODEL / 4) + j] = o;
#pragma unroll
            for (int e = 0; e < N_EXP; e++)
                acc[t][e] += v.x * w[e].x + v.y * w[e].y + v.z * w[e].z + v.w * w[e].w;
        }
    }
#pragma unroll
    for (int t = 0; t < 4; t++)
#pragma unroll
        for (int e = 0; e < N_EXP; e++) {
#pragma unroll
            for (int s = 16; s > 0; s >>= 1)
                acc[t][e] += __shfl_xor_sync(0xffffffff, acc[t][e], s);
        }
    if (lane == 0) {
#pragma unroll
        for (int t = 0; t < 4; t++) {
            float lg[N_EXP];
            float mx = -1e30f;
            int mi = 0;
#pragma unroll
            for (int e = 0; e < N_EXP; e++) {
                lg[e] = acc[t][e] + br[e];
                if (lg[e] > mx) { mx = lg[e]; mi = e; }
            }
            float s = 0.f;
#pragma unroll
            for (int e = 0; e < N_EXP; e++) s += expf(lg[e] - mx);
            float topp = 1.f / s;
            g_idx[t0 + t] = mi;
            g_topp[t0 + t] = topp;
            atomicAdd(&g_cnt[mi], 1);
            atomicAdd(&g_tsum[mi], topp);
        }
    }
}

// scatter + fused loss write; expert offsets computed locally (prefix over 8)
__global__ void scatter_loss_kernel(float* __restrict__ out, int out_size) {
    if (blockIdx.x == 0 && threadIdx.x == 0) {
        double loss = 0.0;
        for (int e = 0; e < N_EXP; e++) {
            double fr = (double)g_cnt[e] / (double)T_TOK;
            double pr = (double)g_tsum[e] / ((double)T_TOK * (double)T_TOK);
            loss += fr * pr;
        }
        loss *= (double)LOSS_SCALE * (double)N_EXP;
        long long ysz = (long long)T_TOK * D_MODEL;
        if ((long long)out_size > ysz) out[ysz] = (float)loss;
    }
    int t = blockIdx.x * blockDim.x + threadIdx.x;
    if (t >= T_TOK) return;
    int e = g_idx[t];
    int off = 0;
#pragma unroll
    for (int k = 0; k < N_EXP; k++) off += (k < e) ? g_cnt[k] : 0;
    int pos = off + atomicAdd(&g_cur[e], 1);
    g_list[pos] = t;
}

// ---------------- grouped GEMM: BM=128 x BN=256, 512 thr, 4-stage, 1 CTA/SM --
// Per stage: A 128x128B (16KB) + B 256x128B (32KB) = 48KB. 4 stages = 192KB.
#define STG 49152
#define B_OFF 16384
#define NSTAGE 4
#define SM_META (NSTAGE * STG)
#define GEMM_SMEM (SM_META + 2048)

__global__ __launch_bounds__(NTHREADS, 1)
void moe_gemm_kernel(const float* __restrict__ bias, float* __restrict__ out) {
    const int e = blockIdx.y;
    const int n_e = g_cnt[e];
    const int tile = blockIdx.x;
    if (tile * BM >= n_e) return;
    const int ntile = blockIdx.z;    // 0..7 over BN=256 slabs

    int off_e = 0;
#pragma unroll
    for (int k = 0; k < N_EXP; k++) off_e += (k < e) ? g_cnt[k] : 0;

    extern __shared__ char smem[];
    const uint32_t smem_base = smem_u32(smem);
    int* s_tok = (int*)(smem + SM_META);
    float* s_topp = (float*)(smem + SM_META + 512);
    float* s_bias = (float*)(smem + SM_META + 1024);

    const int tid = threadIdx.x;
    const int lane = tid & 31;
    const int wid = tid >> 5;   // 0..15
    const int wm = wid & 3;     // 4 m-groups of 32 rows
    const int wn = wid >> 2;    // 4 n-groups of 64 cols

    int n_rem = n_e - tile * BM;
    if (n_rem > BM) n_rem = BM;
    const int base_pos = off_e + tile * BM;
    if (tid < BM) {
        int r = (tid < n_rem) ? tid : (n_rem - 1);
        int tk = g_list[base_pos + r];
        s_tok[tid] = tk;
        s_topp[tid] = g_topp[tk];
    }
    if (tid < BN) s_bias[tid] = bias[e * D_MODEL + ntile * BN + tid];
    __syncthreads();

    // cp.async mapping (512 thr): crow = tid>>3 (0..63), cc = tid&7 (16B chunk)
    // A: rows crow, crow+64 (2 chunks). B: rows crow+64j, j=0..3 (4 chunks).
    const int crow = tid >> 3;
    const int cc = tid & 7;
    const __half* aSrc[2];
    uint32_t aOff[2];
#pragma unroll
    for (int j = 0; j < 2; j++) {
        int row = crow + 64 * j;
        int tk = s_tok[row];
        aSrc[j] = g_Xh + (size_t)tk * D_MODEL + cc * 8;
        aOff[j] = (uint32_t)(row * 128 + ((cc * 16) ^ ((row & 7) << 4)));
    }
    const __half* bSrc[4];
    uint32_t bOff[4];
#pragma unroll
    for (int j = 0; j < 4; j++) {
        int row = crow + 64 * j;
        size_t wrow = (size_t)e * D_MODEL + ntile * BN + row;
        bSrc[j] = g_Wh + wrow * D_MODEL + cc * 8;
        bOff[j] = (uint32_t)(row * 128 + ((cc * 16) ^ ((row & 7) << 4)));
    }

    auto issue_copies = [&](int it) {
        uint32_t sb = smem_base + (uint32_t)(it % NSTAGE) * STG;
        size_t koff = (size_t)it * BK;
#pragma unroll
        for (int j = 0; j < 2; j++)
            CP_ASYNC16(sb + aOff[j], aSrc[j] + koff);
#pragma unroll
        for (int j = 0; j < 4; j++)
            CP_ASYNC16(sb + B_OFF + bOff[j], bSrc[j] + koff);
    };

    // ldmatrix lane addressing (SW128: addr = row*128 + (kbyte ^ ((row&7)<<4)))
    const int rA = wm * 32 + ((lane >> 3) & 1) * 8 + (lane & 7);
    const uint32_t kA = ((lane >> 4) & 1) * 16;
    const uint32_t swA = (uint32_t)((rA & 7) << 4);
    const int rB0 = wn * 64 + ((lane >> 4) & 1) * 8 + (lane & 7);
    const uint32_t kB = ((lane >> 3) & 1) * 16;
    const uint32_t swB = (uint32_t)((lane & 7) << 4);

    float acc[2][8][4];
#pragma unroll
    for (int mt = 0; mt < 2; mt++)
#pragma unroll
        for (int nt = 0; nt < 8; nt++)
#pragma unroll
            for (int k = 0; k < 4; k++) acc[mt][nt][k] = 0.f;

    // prologue: S-1 = 3 stages in flight
    issue_copies(0); CP_COMMIT();
    issue_copies(1); CP_COMMIT();
    issue_copies(2); CP_COMMIT();

    for (int it = 0; it < KIT; it++) {
        CP_WAIT2();           // stage (it) landed (<=2 newer groups pending)
        __syncthreads();      // all warps done reading slot (it-1)%4

        // refill the slot just vacated: stage it+3 -> slot (it-1)%4
        if (it + NSTAGE - 1 < KIT) issue_copies(it + NSTAGE - 1);
        CP_COMMIT();          // commit (possibly empty) to keep group counts

        const uint32_t stb = smem_base + (uint32_t)(it % NSTAGE) * STG;
#pragma unroll
        for (int ks = 0; ks < 4; ks++) {
            const uint32_t kxA = (uint32_t)(ks * 32 + kA) ^ swA;
            uint32_t ah[2][4];
#pragma unroll
            for (int mt = 0; mt < 2; mt++) {
                uint32_t ab = stb + (uint32_t)((rA + mt * 16) * 128) + kxA;
                ldsm4(ah[mt][0], ah[mt][1], ah[mt][2], ah[mt][3], ab);
            }
            const uint32_t kxB = (uint32_t)(ks * 32 + kB) ^ swB;
#pragma unroll
            for (int p = 0; p < 4; p++) {
                uint32_t bb = stb + B_OFF + (uint32_t)((rB0 + p * 16) * 128) + kxB;
                uint32_t bh[4];
                ldsm4(bh[0], bh[1], bh[2], bh[3], bb);
#pragma unroll
                for (int mt = 0; mt < 2; mt++) {
                    mma16816(acc[mt][2 * p],     ah[mt], bh[0], bh[1]);
                    mma16816(acc[mt][2 * p + 1], ah[mt], bh[2], bh[3]);
                }
            }
        }
    }

    // epilogue: +bias, *topp, scatter by token
#pragma unroll
    for (int mt = 0; mt < 2; mt++) {
#pragma unroll
        for (int half = 0; half < 2; half++) {
            int row = wm * 32 + mt * 16 + (lane >> 2) + half * 8;
            if (row < n_rem) {
                int tk = s_tok[row];
                float tp = s_topp[row];
                float* op = out + (size_t)tk * D_MODEL + ntile * BN;
#pragma unroll
                for (int nt = 0; nt < 8; nt++) {
                    int col = wn * 64 + nt * 8 + (lane & 3) * 2;
                    float2 v;
                    v.x = (acc[mt][nt][half * 2 + 0] + s_bias[col]) * tp;
                    v.y = (acc[mt][nt][half * 2 + 1] + s_bias[col + 1]) * tp;
                    *(float2*)(op + col) = v;
                }
            }
        }
    }
}

// ---------------- launcher ---------------------------------------------------
extern "C" void kernel_launch(void* const* d_in, const int* in_sizes, int n_in,
                              void* d_out, int out_size) {
    const float* x  = (const float*)d_in[0];
    const float* Wr = (const float*)d_in[1];
    const float* br = (const float*)d_in[2];
    const float* W  = (const float*)d_in[3];
    const float* b  = (const float*)d_in[4];
    float* out = (float*)d_out;

    cudaFuncSetAttribute(moe_gemm_kernel,
                         cudaFuncAttributeMaxDynamicSharedMemorySize, GEMM_SMEM);

    init_kernel<<<1, 32>>>();
    router_convert_kernel<<<ROUTER_BLOCKS + CONV_BLOCKS, 256>>>(
        x, Wr, br, (const float4*)W);
    scatter_loss_kernel<<<T_TOK / 256, 256>>>(out, out_size);
    dim3 grid(T_TOK / BM, N_EXP, D_MODEL / BN);
    moe_gemm_kernel<<<grid, NTHREADS, GEMM_SMEM>>>(b, out);
}

// round 15
// speedup vs baseline: 1.0521x; 1.0521x over previous
#include <cuda_runtime.h>
#include <cuda_fp16.h>
#include <cstdint>
#include <cstddef>

#define D_MODEL 2048
#define N_EXP 8
#define T_TOK 8192
#define BM 128
#define BN 128
#define BK 64
#define KIT (D_MODEL / BK)
#define NTHREADS 256
#define LOSS_SCALE 3e-06f
#define TOK_PER_WARP 2
#define ROUTER_BLOCKS (T_TOK / (TOK_PER_WARP * 8))  /* 512 blocks, 8 warps each */
#define CONV_BLOCKS 8192

// ---------------- device global scratch (no allocations allowed) ------------
__device__ int   g_cnt[N_EXP];
__device__ int   g_cur[N_EXP];
__device__ float g_tsum[N_EXP];
__device__ int   g_idx[T_TOK];
__device__ float g_topp[T_TOK];
__device__ int   g_list[T_TOK];

// fp16 copies, precomputed once per launch
__device__ __half g_Wh[(size_t)N_EXP * D_MODEL * D_MODEL];
__device__ __half g_Xh[(size_t)T_TOK * D_MODEL];

// ---------------- helpers ----------------------------------------------------
__device__ __forceinline__ uint32_t smem_u32(const void* p) {
    uint32_t a;
    asm("{ .reg .u64 t; cvta.to.shared.u64 t, %1; cvt.u32.u64 %0, t; }"
        : "=r"(a) : "l"(p));
    return a;
}

#define CP_ASYNC16(dst, src) \
    asm volatile("cp.async.cg.shared.global [%0], [%1], 16;" \
        :: "r"(dst), "l"(src))
#define CP_COMMIT() asm volatile("cp.async.commit_group;")
#define CP_WAIT1()  asm volatile("cp.async.wait_group 1;")

__device__ __forceinline__ void ldsm4(uint32_t& r0, uint32_t& r1, uint32_t& r2,
                                      uint32_t& r3, uint32_t addr) {
    asm volatile("ldmatrix.sync.aligned.m8n8.x4.shared.b16 {%0,%1,%2,%3}, [%4];"
                 : "=r"(r0), "=r"(r1), "=r"(r2), "=r"(r3) : "r"(addr));
}

__device__ __forceinline__ void mma16816(float* c, const uint32_t* a,
                                         uint32_t b0, uint32_t b1) {
    asm volatile(
        "mma.sync.aligned.m16n8k16.row.col.f32.f16.f16.f32 "
        "{%0,%1,%2,%3}, {%4,%5,%6,%7}, {%8,%9}, {%0,%1,%2,%3};"
        : "+f"(c[0]), "+f"(c[1]), "+f"(c[2]), "+f"(c[3])
        : "r"(a[0]), "r"(a[1]), "r"(a[2]), "r"(a[3]), "r"(b0), "r"(b1));
}

__device__ __forceinline__ uint2 cvt_f4(float4 v) {
    __half2 h0 = __floats2half2_rn(v.x, v.y);
    __half2 h1 = __floats2half2_rn(v.z, v.w);
    uint2 o;
    o.x = *(uint32_t*)&h0;
    o.y = *(uint32_t*)&h1;
    return o;
}

// ---------------- small kernels ----------------------------------------------
__global__ void init_kernel() {
    int i = threadIdx.x;
    if (i < N_EXP) { g_cnt[i] = 0; g_cur[i] = 0; g_tsum[i] = 0.f; }
}

// Fused kernel: blocks [0, ROUTER_BLOCKS) run the router (+ x->fp16 store),
// blocks [ROUTER_BLOCKS, ...) convert W to fp16 with MLP=4 batched loads.
__global__ void router_convert_kernel(const float* __restrict__ x,
                                      const float* __restrict__ Wr,
                                      const float* __restrict__ br,
                                      const float4* __restrict__ W4) {
    if (blockIdx.x >= ROUTER_BLOCKS) {
        // ---- convert path: 4 float4 per thread per iter, loads batched ----
        uint2* wh2 = reinterpret_cast<uint2*>(g_Wh);
        const int ngrp = N_EXP * D_MODEL * D_MODEL / 16;  // groups of 4 float4
        int bi = blockIdx.x - ROUTER_BLOCKS;
        for (int g = bi * blockDim.x + threadIdx.x; g < ngrp;
             g += CONV_BLOCKS * blockDim.x) {
            int i = g * 4;
            float4 v0 = W4[i + 0];
            float4 v1 = W4[i + 1];
            float4 v2 = W4[i + 2];
            float4 v3 = W4[i + 3];
            uint2 o0 = cvt_f4(v0), o1 = cvt_f4(v1);
            uint2 o2 = cvt_f4(v2), o3 = cvt_f4(v3);
            wh2[i + 0] = o0;
            wh2[i + 1] = o1;
            wh2[i + 2] = o2;
            wh2[i + 3] = o3;
        }
        return;
    }

    // ---- router path: one warp per TOK_PER_WARP tokens ----
    int warp = (blockIdx.x * blockDim.x + threadIdx.x) >> 5;
    int lane = threadIdx.x & 31;
    int t0 = warp * TOK_PER_WARP;
    if (t0 >= T_TOK) return;

    const float4* x4 = reinterpret_cast<const float4*>(x);
    const float4* w4 = reinterpret_cast<const float4*>(Wr);
    uint2* xh2 = reinterpret_cast<uint2*>(g_Xh);

    float acc[TOK_PER_WARP][N_EXP];
#pragma unroll
    for (int t = 0; t < TOK_PER_WARP; t++)
#pragma unroll
        for (int e = 0; e < N_EXP; e++) acc[t][e] = 0.f;

    for (int j = lane; j < D_MODEL / 4; j += 32) {
        float4 w[N_EXP];
#pragma unroll
        for (int e = 0; e < N_EXP; e++) w[e] = w4[e * (D_MODEL / 4) + j];
#pragma unroll
        for (int t = 0; t < TOK_PER_WARP; t++) {
            float4 v = x4[(size_t)(t0 + t) * (D_MODEL / 4) + j];
            xh2[(size_t)(t0 + t) * (D_MODEL / 4) + j] = cvt_f4(v);
#pragma unroll
            for (int e = 0; e < N_EXP; e++)
                acc[t][e] += v.x * w[e].x + v.y * w[e].y + v.z * w[e].z + v.w * w[e].w;
        }
    }
#pragma unroll
    for (int t = 0; t < TOK_PER_WARP; t++)
#pragma unroll
        for (int e = 0; e < N_EXP; e++) {
#pragma unroll
            for (int s = 16; s > 0; s >>= 1)
                acc[t][e] += __shfl_xor_sync(0xffffffff, acc[t][e], s);
        }
    if (lane == 0) {
#pragma unroll
        for (int t = 0; t < TOK_PER_WARP; t++) {
            float lg[N_EXP];
            float mx = -1e30f;
            int mi = 0;
#pragma unroll
            for (int e = 0; e < N_EXP; e++) {
                lg[e] = acc[t][e] + br[e];
                if (lg[e] > mx) { mx = lg[e]; mi = e; }
            }
            float s = 0.f;
#pragma unroll
            for (int e = 0; e < N_EXP; e++) s += expf(lg[e] - mx);
            float topp = 1.f / s;
            g_idx[t0 + t] = mi;
            g_topp[t0 + t] = topp;
            atomicAdd(&g_cnt[mi], 1);
            atomicAdd(&g_tsum[mi], topp);
        }
    }
}

// scatter + fused loss write; expert offsets computed locally (prefix over 8)
__global__ void scatter_loss_kernel(float* __restrict__ out, int out_size) {
    if (blockIdx.x == 0 && threadIdx.x == 0) {
        double loss = 0.0;
        for (int e = 0; e < N_EXP; e++) {
            double fr = (double)g_cnt[e] / (double)T_TOK;
            double pr = (double)g_tsum[e] / ((double)T_TOK * (double)T_TOK);
            loss += fr * pr;
        }
        loss *= (double)LOSS_SCALE * (double)N_EXP;
        long long ysz = (long long)T_TOK * D_MODEL;
        if ((long long)out_size > ysz) out[ysz] = (float)loss;
    }
    int t = blockIdx.x * blockDim.x + threadIdx.x;
    if (t >= T_TOK) return;
    int e = g_idx[t];
    int off = 0;
#pragma unroll
    for (int k = 0; k < N_EXP; k++) off += (k < e) ? g_cnt[k] : 0;
    int pos = off + atomicAdd(&g_cur[e], 1);
    g_list[pos] = t;
}

// ---------------- grouped GEMM (round-12 config: BM128xBN128, 3-stage, ------
// ---------------- 256 thr, 2 CTA/SM, single-sync multistage loop) -----------
#define STG 32768
#define B_OFF 16384
#define NSTAGE 3
#define SM_META (NSTAGE * STG)
#define GEMM_SMEM (SM_META + 1536)

__global__ __launch_bounds__(NTHREADS, 2)
void moe_gemm_kernel(const float* __restrict__ bias, float* __restrict__ out) {
    const int e = blockIdx.y;
    const int n_e = g_cnt[e];
    const int tile = blockIdx.x;
    if (tile * BM >= n_e) return;
    const int ntile = blockIdx.z;

    int off_e = 0;
#pragma unroll
    for (int k = 0; k < N_EXP; k++) off_e += (k < e) ? g_cnt[k] : 0;

    extern __shared__ char smem[];
    const uint32_t smem_base = smem_u32(smem);
    int* s_tok = (int*)(smem + SM_META);
    float* s_topp = (float*)(smem + SM_META + 512);
    float* s_bias = (float*)(smem + SM_META + 1024);

    const int tid = threadIdx.x;
    const int lane = tid & 31;
    const int wid = tid >> 5;
    const int wm = wid & 3;   // 4 m-groups of 32 rows
    const int wn = wid >> 2;  // 2 n-groups of 64 cols

    int n_rem = n_e - tile * BM;
    if (n_rem > BM) n_rem = BM;
    const int base_pos = off_e + tile * BM;
    if (tid < BM) {
        int r = (tid < n_rem) ? tid : (n_rem - 1);
        int tk = g_list[base_pos + r];
        s_tok[tid] = tk;
        s_topp[tid] = g_topp[tk];
    }
    if (tid < BN) s_bias[tid] = bias[e * D_MODEL + ntile * BN + tid];
    __syncthreads();

    // cp.async mapping: thread t -> rows (t>>3)+32j, 16B chunk (t&7); SW128 dst
    const int crow = tid >> 3;
    const int cc = tid & 7;
    const __half* aSrc[4];
    const __half* bSrc[4];
    uint32_t dstOff[4];
#pragma unroll
    for (int j = 0; j < 4; j++) {
        int row = crow + 32 * j;
        int tk = s_tok[row];
        aSrc[j] = g_Xh + (size_t)tk * D_MODEL + cc * 8;
        size_t wrow = (size_t)e * D_MODEL + ntile * BN + row;
        bSrc[j] = g_Wh + wrow * D_MODEL + cc * 8;
        dstOff[j] = (uint32_t)(row * 128 + ((cc * 16) ^ ((row & 7) << 4)));
    }

    auto issue_copies = [&](int it) {
        uint32_t sb = smem_base + (uint32_t)(it % NSTAGE) * STG;
        size_t koff = (size_t)it * BK;
#pragma unroll
        for (int j = 0; j < 4; j++) {
            CP_ASYNC16(sb + dstOff[j], aSrc[j] + koff);
            CP_ASYNC16(sb + B_OFF + dstOff[j], bSrc[j] + koff);
        }
    };

    // ldmatrix lane addressing (SW128: addr = row*128 + (kbyte ^ ((row&7)<<4)))
    const int rA = wm * 32 + ((lane >> 3) & 1) * 8 + (lane & 7);
    const uint32_t kA = ((lane >> 4) & 1) * 16;
    const uint32_t swA = (uint32_t)((rA & 7) << 4);
    const int rB0 = wn * 64 + ((lane >> 4) & 1) * 8 + (lane & 7);
    const uint32_t kB = ((lane >> 3) & 1) * 16;
    const uint32_t swB = (uint32_t)((lane & 7) << 4);

    float acc[2][8][4];
#pragma unroll
    for (int mt = 0; mt < 2; mt++)
#pragma unroll
        for (int nt = 0; nt < 8; nt++)
#pragma unroll
            for (int k = 0; k < 4; k++) acc[mt][nt][k] = 0.f;

    // prologue: S-1 = 2 stages in flight
    issue_copies(0); CP_COMMIT();
    issue_copies(1); CP_COMMIT();

    for (int it = 0; it < KIT; it++) {
        CP_WAIT1();           // stage (it) landed (<=1 newer group pending)
        __syncthreads();      // also: all warps done reading slot (it-1)%3

        // refill the slot just vacated: stage it+2 -> slot (it-1)%3
        if (it + NSTAGE - 1 < KIT) issue_copies(it + NSTAGE - 1);
        CP_COMMIT();          // commit (possibly empty) to keep group counts

        const uint32_t stb = smem_base + (uint32_t)(it % NSTAGE) * STG;
#pragma unroll
        for (int ks = 0; ks < 4; ks++) {
            const uint32_t kxA = (uint32_t)(ks * 32 + kA) ^ swA;
            uint32_t ah[2][4];
#pragma unroll
            for (int mt = 0; mt < 2; mt++) {
                uint32_t ab = stb + (uint32_t)((rA + mt * 16) * 128) + kxA;
                ldsm4(ah[mt][0], ah[mt][1], ah[mt][2], ah[mt][3], ab);
            }
            const uint32_t kxB = (uint32_t)(ks * 32 + kB) ^ swB;
#pragma unroll
            for (int p = 0; p < 4; p++) {
                uint32_t bb = stb + B_OFF + (uint32_t)((rB0 + p * 16) * 128) + kxB;
                uint32_t bh[4];
                ldsm4(bh[0], bh[1], bh[2], bh[3], bb);
#pragma unroll
                for (int mt = 0; mt < 2; mt++) {
                    mma16816(acc[mt][2 * p],     ah[mt], bh[0], bh[1]);
                    mma16816(acc[mt][2 * p + 1], ah[mt], bh[2], bh[3]);
                }
            }
        }
    }

    // epilogue: +bias, *topp, scatter by token
#pragma unroll
    for (int mt = 0; mt < 2; mt++) {
#pragma unroll
        for (int half = 0; half < 2; half++) {
            int row = wm * 32 + mt * 16 + (lane >> 2) + half * 8;
            if (row < n_rem) {
                int tk = s_tok[row];
                float tp = s_topp[row];
                float* op = out + (size_t)tk * D_MODEL + ntile * BN;
#pragma unroll
                for (int nt = 0; nt < 8; nt++) {
                    int col = wn * 64 + nt * 8 + (lane & 3) * 2;
                    float2 v;
                    v.x = (acc[mt][nt][half * 2 + 0] + s_bias[col]) * tp;
                    v.y = (acc[mt][nt][half * 2 + 1] + s_bias[col + 1]) * tp;
                    *(float2*)(op + col) = v;
                }
            }
        }
    }
}

// ---------------- launcher ---------------------------------------------------
extern "C" void kernel_launch(void* const* d_in, const int* in_sizes, int n_in,
                              void* d_out, int out_size) {
    const float* x  = (const float*)d_in[0];
    const float* Wr = (const float*)d_in[1];
    const float* br = (const float*)d_in[2];
    const float* W  = (const float*)d_in[3];
    const float* b  = (const float*)d_in[4];
    float* out = (float*)d_out;

    cudaFuncSetAttribute(moe_gemm_kernel,
                         cudaFuncAttributeMaxDynamicSharedMemorySize, GEMM_SMEM);

    init_kernel<<<1, 32>>>();
    router_convert_kernel<<<ROUTER_BLOCKS + CONV_BLOCKS, 256>>>(
        x, Wr, br, (const float4*)W);
    scatter_loss_kernel<<<T_TOK / 256, 256>>>(out, out_size);
    dim3 grid(T_TOK / BM, N_EXP, D_MODEL / BN);
    moe_gemm_kernel<<<grid, NTHREADS, GEMM_SMEM>>>(b, out);
}